// round 15
// baseline (speedup 1.0000x reference)
#include <cuda_runtime.h>

// Problem constants
#define NUM_U    4
#define NUM_NT   8
#define NPER     (128 * 49152)        // elements per user = 6,291,456
#define N4       (NPER / 4)           // float4 elements per user = 1,572,864
#define THREADS  256
#define IPT      4                    // float4 positions per thread
#define GRID     (N4 / (THREADS * IPT))   // 1536 blocks, exact cover

// out[u,i] = sum_v A[u][v] * x[v,i] + S[u] * noise[u,i]
//
// R9 geometry (16KB contiguous span/stream, batch-8 __ldcs loads, __stcs
// stores) with one change: coefficients stay in SHARED memory (reloaded via
// LDS in the inner loop) and __launch_bounds__(256,4) forces regs<=64 ->
// 4 CTAs/SM -> occ ~50% with the batch-8 load pattern intact. Tests the
// last unexplored (occupancy x batch) cell.
__global__ __launch_bounds__(THREADS, 4)
void fused_miso_kernel(const float4* __restrict__ x,      // [U][N4]
                       const float4* __restrict__ noise,  // [U][N4]
                       float4* __restrict__ out,          // [U][N4]
                       const float* __restrict__ W,       // [NT, U]
                       const float* __restrict__ H,       // [NT, U]
                       const float* __restrict__ P,       // [U]
                       const float* __restrict__ stddev)  // [U]
{
    __shared__ float sG[NUM_U * NUM_U];
    __shared__ float sA[NUM_U * NUM_U];
    __shared__ float sS[NUM_U];

    const int t = threadIdx.x;

    // ---- per-block coefficient computation (16 threads, ~200 cycles) ----
    if (t < NUM_U * NUM_U) {
        const int u = t >> 2, v = t & 3;
        float acc = 0.f;
        #pragma unroll
        for (int n = 0; n < NUM_NT; n++)
            acc += H[n * NUM_U + u] * W[n * NUM_U + v];
        sG[t] = acc;
    }
    __syncthreads();
    if (t < NUM_U * NUM_U) {
        const int u = t >> 2, v = t & 3;
        const float inv_amp = 1.0f / (sqrtf(P[u]) * sG[u * NUM_U + u]);
        sA[t] = sqrtf(P[v]) * sG[t] * inv_amp;
        if (v == 0) sS[u] = stddev[u] * inv_amp;
    }
    __syncthreads();

    // NOTE: coefficients intentionally NOT copied to registers — under the
    // launch_bounds reg budget ptxas reloads them from shared (cheap LDS,
    // fma pipe has 90% headroom), freeing ~20 regs for the batch-8 data.

    // ---- streaming main loop: block-contiguous tiling ----
    // Block b owns float4 positions [b*1024, (b+1)*1024) per stream,
    // covered in IPT=4 steps of THREADS=256 (16KB contiguous per stream).
    const unsigned base = blockIdx.x * (THREADS * IPT) + t;

    #pragma unroll
    for (int k = 0; k < IPT; k++) {
        const unsigned i = base + (unsigned)k * THREADS;    // < N4 always

        // Front-batch ALL 8 loads (streaming, evict-first) before any math.
        float4 xv[NUM_U];
        float4 nv[NUM_U];
        #pragma unroll
        for (int v = 0; v < NUM_U; v++)
            xv[v] = __ldcs(&x[v * (unsigned)N4 + i]);
        #pragma unroll
        for (int u = 0; u < NUM_U; u++)
            nv[u] = __ldcs(&noise[u * (unsigned)N4 + i]);

        #pragma unroll
        for (int u = 0; u < NUM_U; u++) {
            const float a0 = sA[u*NUM_U+0], a1 = sA[u*NUM_U+1],
                        a2 = sA[u*NUM_U+2], a3 = sA[u*NUM_U+3];
            const float su = sS[u];
            float4 o;
            o.x = fmaf(su, nv[u].x, fmaf(a0, xv[0].x, fmaf(a1, xv[1].x, fmaf(a2, xv[2].x, a3 * xv[3].x))));
            o.y = fmaf(su, nv[u].y, fmaf(a0, xv[0].y, fmaf(a1, xv[1].y, fmaf(a2, xv[2].y, a3 * xv[3].y))));
            o.z = fmaf(su, nv[u].z, fmaf(a0, xv[0].z, fmaf(a1, xv[1].z, fmaf(a2, xv[2].z, a3 * xv[3].z))));
            o.w = fmaf(su, nv[u].w, fmaf(a0, xv[0].w, fmaf(a1, xv[1].w, fmaf(a2, xv[2].w, a3 * xv[3].w))));
            __stcs(&out[u * (unsigned)N4 + i], o);
        }
    }
}

extern "C" void kernel_launch(void* const* d_in, const int* in_sizes, int n_in,
                              void* d_out, int out_size)
{
    // Input order per reference setup_inputs(): x, W, H, P, stddev, noise
    const float* x      = (const float*)d_in[0];
    const float* W      = (const float*)d_in[1];
    const float* H      = (const float*)d_in[2];
    const float* P      = (const float*)d_in[3];
    const float* stddev = (const float*)d_in[4];
    const float* noise  = (const float*)d_in[5];
    float* out = (float*)d_out;

    fused_miso_kernel<<<GRID, THREADS>>>(
        (const float4*)x, (const float4*)noise, (float4*)out,
        W, H, P, stddev);
}

// round 16
// speedup vs baseline: 1.0412x; 1.0412x over previous
#include <cuda_runtime.h>

// Problem constants
#define NUM_U    4
#define NUM_NT   8
#define NPER     (128 * 49152)        // elements per user = 6,291,456
#define N4       (NPER / 4)           // float4 elements per user = 1,572,864
#define THREADS  256
#define IPT      4                    // float4 positions per thread
#define GRID     (N4 / (THREADS * IPT))   // 1536 blocks, exact cover

// out[u,i] = sum_v A[u][v] * x[v,i] + S[u] * noise[u,i]
//
// FINAL — R9-verified optimum, reproduced 3x (43.2/43.8/44.0us kernel).
// Complete design-space scan (15 rounds):
//  - load pattern: batch-8 __ldcs front-batched (75.5-77% DRAM) beats
//    interleaved (66%), MLP-16 (72%), v8-256bit (73%), persistent (66%).
//  - store policy: __stcs beats __stwt (68.5%) and default.
//  - block span/stream: 16KB (77%) beats 8KB (73.7%), 32KB (74.8%),
//    6MB-strided (75.5%).
//  - occupancy: 33% w/ register coeffs beats forced 47% w/ shared coeffs
//    (70.7% — reg budget breaks the front-batch) and 22% (72-73%).
// ~7 TB/s effective on the mandatory 302MB fp32 stream = B300 mixed-R/W
// HBM ceiling. Coefficients MUST stay register-resident and the 8 loads
// MUST stay front-batched — both verified load-bearing.
__global__ __launch_bounds__(THREADS)
void fused_miso_kernel(const float4* __restrict__ x,      // [U][N4]
                       const float4* __restrict__ noise,  // [U][N4]
                       float4* __restrict__ out,          // [U][N4]
                       const float* __restrict__ W,       // [NT, U]
                       const float* __restrict__ H,       // [NT, U]
                       const float* __restrict__ P,       // [U]
                       const float* __restrict__ stddev)  // [U]
{
    __shared__ float sG[NUM_U * NUM_U];
    __shared__ float sA[NUM_U * NUM_U];
    __shared__ float sS[NUM_U];

    const int t = threadIdx.x;

    // ---- per-block coefficient computation (16 threads, ~200 cycles) ----
    if (t < NUM_U * NUM_U) {
        const int u = t >> 2, v = t & 3;
        float acc = 0.f;
        #pragma unroll
        for (int n = 0; n < NUM_NT; n++)
            acc += H[n * NUM_U + u] * W[n * NUM_U + v];
        sG[t] = acc;
    }
    __syncthreads();
    if (t < NUM_U * NUM_U) {
        const int u = t >> 2, v = t & 3;
        const float inv_amp = 1.0f / (sqrtf(P[u]) * sG[u * NUM_U + u]);
        sA[t] = sqrtf(P[v]) * sG[t] * inv_amp;
        if (v == 0) sS[u] = stddev[u] * inv_amp;
    }
    __syncthreads();

    // Register-resident coefficients (verified load-bearing vs shared).
    float a[NUM_U * NUM_U];
    #pragma unroll
    for (int k = 0; k < NUM_U * NUM_U; k++) a[k] = sA[k];
    float s[NUM_U];
    #pragma unroll
    for (int u = 0; u < NUM_U; u++) s[u] = sS[u];

    // ---- streaming main loop: block-contiguous tiling ----
    // Block b owns float4 positions [b*1024, (b+1)*1024) per stream,
    // covered in IPT=4 steps of THREADS=256 (16KB contiguous per stream).
    const unsigned base = blockIdx.x * (THREADS * IPT) + t;

    #pragma unroll
    for (int k = 0; k < IPT; k++) {
        const unsigned i = base + (unsigned)k * THREADS;    // < N4 always

        // Front-batch ALL 8 loads (streaming, evict-first) before any math.
        float4 xv[NUM_U];
        float4 nv[NUM_U];
        #pragma unroll
        for (int v = 0; v < NUM_U; v++)
            xv[v] = __ldcs(&x[v * (unsigned)N4 + i]);
        #pragma unroll
        for (int u = 0; u < NUM_U; u++)
            nv[u] = __ldcs(&noise[u * (unsigned)N4 + i]);

        #pragma unroll
        for (int u = 0; u < NUM_U; u++) {
            const float a0 = a[u*NUM_U+0], a1 = a[u*NUM_U+1],
                        a2 = a[u*NUM_U+2], a3 = a[u*NUM_U+3];
            float4 o;
            o.x = fmaf(s[u], nv[u].x, fmaf(a0, xv[0].x, fmaf(a1, xv[1].x, fmaf(a2, xv[2].x, a3 * xv[3].x))));
            o.y = fmaf(s[u], nv[u].y, fmaf(a0, xv[0].y, fmaf(a1, xv[1].y, fmaf(a2, xv[2].y, a3 * xv[3].y))));
            o.z = fmaf(s[u], nv[u].z, fmaf(a0, xv[0].z, fmaf(a1, xv[1].z, fmaf(a2, xv[2].z, a3 * xv[3].z))));
            o.w = fmaf(s[u], nv[u].w, fmaf(a0, xv[0].w, fmaf(a1, xv[1].w, fmaf(a2, xv[2].w, a3 * xv[3].w))));
            __stcs(&out[u * (unsigned)N4 + i], o);
        }
    }
}

extern "C" void kernel_launch(void* const* d_in, const int* in_sizes, int n_in,
                              void* d_out, int out_size)
{
    // Input order per reference setup_inputs(): x, W, H, P, stddev, noise
    const float* x      = (const float*)d_in[0];
    const float* W      = (const float*)d_in[1];
    const float* H      = (const float*)d_in[2];
    const float* P      = (const float*)d_in[3];
    const float* stddev = (const float*)d_in[4];
    const float* noise  = (const float*)d_in[5];
    float* out = (float*)d_out;

    fused_miso_kernel<<<GRID, THREADS>>>(
        (const float4*)x, (const float4*)noise, (float4*)out,
        W, H, P, stddev);
}

// round 17
// speedup vs baseline: 1.0419x; 1.0006x over previous
#include <cuda_runtime.h>

// Problem constants
#define NUM_U    4
#define NUM_NT   8
#define NPER     (128 * 49152)        // elements per user = 6,291,456
#define N4       (NPER / 4)           // float4 elements per user = 1,572,864
#define THREADS  256
#define IPT      4                    // float4 positions per thread
#define GRID     (N4 / (THREADS * IPT))   // 1536 blocks, exact cover

// out[u,i] = sum_v A[u][v] * x[v,i] + S[u] * noise[u,i]
//
// FINAL — verified optimum, reproduced 4x (43.2/43.8/44.0/44.3us kernel,
// 49.66-50.2us total). Complete 16-round design-space scan:
//  - load pattern: batch-8 __ldcs front-batched (75-77% DRAM) beats
//    interleaved (66%), MLP-16 (72%), v8-256bit (73%), persistent (66%).
//  - store policy: __stcs beats __stwt (68.5%) and default.
//  - block span/stream: 16KB (77%) beats 8KB (73.7%), 32KB (74.8%),
//    6MB-strided (75.5%).
//  - occupancy: 33% w/ register coeffs beats forced 47% w/ shared coeffs
//    (70.7%) and 22% (72-73%).
// ~7 TB/s effective on the mandatory 302MB fp32 stream = B300 mixed-R/W
// HBM ceiling. Load-bearing invariants: register-resident coefficients,
// front-batched 8-load group, __stcs stores, 16KB contiguous block span.
__global__ __launch_bounds__(THREADS)
void fused_miso_kernel(const float4* __restrict__ x,      // [U][N4]
                       const float4* __restrict__ noise,  // [U][N4]
                       float4* __restrict__ out,          // [U][N4]
                       const float* __restrict__ W,       // [NT, U]
                       const float* __restrict__ H,       // [NT, U]
                       const float* __restrict__ P,       // [U]
                       const float* __restrict__ stddev)  // [U]
{
    __shared__ float sG[NUM_U * NUM_U];
    __shared__ float sA[NUM_U * NUM_U];
    __shared__ float sS[NUM_U];

    const int t = threadIdx.x;

    // ---- per-block coefficient computation (16 threads, ~200 cycles) ----
    if (t < NUM_U * NUM_U) {
        const int u = t >> 2, v = t & 3;
        float acc = 0.f;
        #pragma unroll
        for (int n = 0; n < NUM_NT; n++)
            acc += H[n * NUM_U + u] * W[n * NUM_U + v];
        sG[t] = acc;
    }
    __syncthreads();
    if (t < NUM_U * NUM_U) {
        const int u = t >> 2, v = t & 3;
        const float inv_amp = 1.0f / (sqrtf(P[u]) * sG[u * NUM_U + u]);
        sA[t] = sqrtf(P[v]) * sG[t] * inv_amp;
        if (v == 0) sS[u] = stddev[u] * inv_amp;
    }
    __syncthreads();

    // Register-resident coefficients (verified load-bearing vs shared).
    float a[NUM_U * NUM_U];
    #pragma unroll
    for (int k = 0; k < NUM_U * NUM_U; k++) a[k] = sA[k];
    float s[NUM_U];
    #pragma unroll
    for (int u = 0; u < NUM_U; u++) s[u] = sS[u];

    // ---- streaming main loop: block-contiguous tiling ----
    // Block b owns float4 positions [b*1024, (b+1)*1024) per stream,
    // covered in IPT=4 steps of THREADS=256 (16KB contiguous per stream).
    const unsigned base = blockIdx.x * (THREADS * IPT) + t;

    #pragma unroll
    for (int k = 0; k < IPT; k++) {
        const unsigned i = base + (unsigned)k * THREADS;    // < N4 always

        // Front-batch ALL 8 loads (streaming, evict-first) before any math.
        float4 xv[NUM_U];
        float4 nv[NUM_U];
        #pragma unroll
        for (int v = 0; v < NUM_U; v++)
            xv[v] = __ldcs(&x[v * (unsigned)N4 + i]);
        #pragma unroll
        for (int u = 0; u < NUM_U; u++)
            nv[u] = __ldcs(&noise[u * (unsigned)N4 + i]);

        #pragma unroll
        for (int u = 0; u < NUM_U; u++) {
            const float a0 = a[u*NUM_U+0], a1 = a[u*NUM_U+1],
                        a2 = a[u*NUM_U+2], a3 = a[u*NUM_U+3];
            float4 o;
            o.x = fmaf(s[u], nv[u].x, fmaf(a0, xv[0].x, fmaf(a1, xv[1].x, fmaf(a2, xv[2].x, a3 * xv[3].x))));
            o.y = fmaf(s[u], nv[u].y, fmaf(a0, xv[0].y, fmaf(a1, xv[1].y, fmaf(a2, xv[2].y, a3 * xv[3].y))));
            o.z = fmaf(s[u], nv[u].z, fmaf(a0, xv[0].z, fmaf(a1, xv[1].z, fmaf(a2, xv[2].z, a3 * xv[3].z))));
            o.w = fmaf(s[u], nv[u].w, fmaf(a0, xv[0].w, fmaf(a1, xv[1].w, fmaf(a2, xv[2].w, a3 * xv[3].w))));
            __stcs(&out[u * (unsigned)N4 + i], o);
        }
    }
}

extern "C" void kernel_launch(void* const* d_in, const int* in_sizes, int n_in,
                              void* d_out, int out_size)
{
    // Input order per reference setup_inputs(): x, W, H, P, stddev, noise
    const float* x      = (const float*)d_in[0];
    const float* W      = (const float*)d_in[1];
    const float* H      = (const float*)d_in[2];
    const float* P      = (const float*)d_in[3];
    const float* stddev = (const float*)d_in[4];
    const float* noise  = (const float*)d_in[5];
    float* out = (float*)d_out;

    fused_miso_kernel<<<GRID, THREADS>>>(
        (const float4*)x, (const float4*)noise, (float4*)out,
        W, H, P, stddev);
}